// round 12
// baseline (speedup 1.0000x reference)
#include <cuda_runtime.h>
#include <cuda_pipeline.h>
#include <stdint.h>

// TopK masking: out = x * mask(top-64 per row), x: [16384, 4096] fp32.
//
// PERSISTENT CTAs (grid 912 = 152 SMs x 6), grid-stride over rows, with a
// cp.async double-buffered smem prefetch: row i+1 streams into the alternate
// 16KB buffer while row i is selected+written, so each CTA keeps DRAM
// requests in flight continuously (no load/compute/store phase gaps, no
// wave transitions). Each thread cp.asyncs exactly the float4s it later
// reads -> per-thread wait_prior(1) suffices, no extra barrier.
// Selection (unchanged from R11, 82.4us): histogram-256 over (1.9,4.46)
// from registers, warp-0 suffix scan, boundary-bin gather, exact augmented
// rank (value desc, col asc) == jax.lax.top_k stable order ->
// bit-deterministic. Exact radix-256 fallback for any out-of-range case.

#define THREADS 256
#define FDIM 4096
#define PER_THREAD 16
#define KSEL 64u
#define TGUESS 1.9f
#define MCAP 256u
#define NCTA 912

__device__ __forceinline__ unsigned int f2key(float f) {
    unsigned int b = __float_as_uint(f);
    return (b & 0x80000000u) ? ~b : (b | 0x80000000u);
}
__device__ __forceinline__ float key2f(unsigned int k) {
    return (k & 0x80000000u) ? __uint_as_float(k & 0x7FFFFFFFu)
                             : __uint_as_float(~k);
}
// deterministic bin: identical fma at every call site; candidates (v>1.9f)
// always have g>0, so trunc == floor and bins form float intervals.
__device__ __forceinline__ float gmap(float v) {
    return __fmaf_rn(v, 100.0f, -190.0f);
}
__device__ __forceinline__ int vbin(float v) {
    int b = (int)gmap(v);
    return b > 255 ? 255 : b;
}

__global__ void __launch_bounds__(THREADS, 6)
topk_mask_kernel(const float* __restrict__ x, float* __restrict__ out,
                 int nrows) {
    const int t = threadIdx.x;

    __shared__ float          buf[2][FDIM];      // 32 KB double buffer
    __shared__ unsigned int   hist[256];
    __shared__ float          mvals[MCAP];
    __shared__ unsigned short mcols[MCAP];
    __shared__ unsigned int   s_total, s_m, s_B, s_r;
    __shared__ float          s_thresh;
    __shared__ unsigned int   s_tcol, s_simple;
    __shared__ unsigned int   s_prefix, s_kth;   // fallback

    // ---- prologue: prefetch first row into buf[0] ----
    int row = blockIdx.x;
    if (row < nrows) {
        const float4* src = reinterpret_cast<const float4*>(x + (size_t)row * FDIM);
        float4*       dst = reinterpret_cast<float4*>(buf[0]);
        #pragma unroll
        for (int v = 0; v < 4; v++)
            __pipeline_memcpy_async(&dst[t + v * THREADS], &src[t + v * THREADS], 16);
    }
    __pipeline_commit();

    int it = 0;
    for (; row < nrows; row += NCTA, it++) {
        const int cur = it & 1;
        const int nxt = cur ^ 1;
        const int nrow = row + NCTA;

        // all threads done with buf[nxt] (read two iterations ago) and with
        // the previous iteration's selection state
        __syncthreads();
        if (t == 0) s_m = 0;
        hist[t] = 0;

        // ---- prefetch next row into buf[nxt] ----
        if (nrow < nrows) {
            const float4* src = reinterpret_cast<const float4*>(x + (size_t)nrow * FDIM);
            float4*       dst = reinterpret_cast<float4*>(buf[nxt]);
            #pragma unroll
            for (int v = 0; v < 4; v++)
                __pipeline_memcpy_async(&dst[t + v * THREADS], &src[t + v * THREADS], 16);
        }
        __pipeline_commit();
        // <=1 group pending -> this thread's copies for buf[cur] are complete
        __pipeline_wait_prior(1);

        // ---- read own values from smem; vals[v*4+j] is column 4t+1024v+j ----
        float vals[PER_THREAD];
        {
            const float4* b4 = reinterpret_cast<const float4*>(buf[cur]);
            #pragma unroll
            for (int v = 0; v < 4; v++) {
                const float4 f4 = b4[t + v * THREADS];
                vals[v * 4 + 0] = f4.x;
                vals[v * 4 + 1] = f4.y;
                vals[v * 4 + 2] = f4.z;
                vals[v * 4 + 3] = f4.w;
            }
        }
        __syncthreads();   // hist zeros + s_m reset visible

        // ---- pass 1: histogram candidates straight from registers ----
        #pragma unroll
        for (int i = 0; i < PER_THREAD; i++) {
            const float v = vals[i];
            if (v > TGUESS) atomicAdd(&hist[vbin(v)], 1u);
        }
        __syncthreads();

        // ---- warp 0: suffix-scan over 256 bins; rank-KSEL bin + total ----
        if (t < 32) {
            const int b0 = t * 8;
            unsigned lsum = 0;
            #pragma unroll
            for (int j = 0; j < 8; j++) lsum += hist[b0 + j];
            unsigned suf = lsum;                  // becomes sum over lanes >= t
            #pragma unroll
            for (int d = 1; d < 32; d <<= 1) {
                const unsigned v = __shfl_down_sync(0xFFFFFFFFu, suf, d);
                if (t + d < 32) suf += v;
            }
            if (t == 0) s_total = suf;            // total candidates
            unsigned run = suf - lsum;            // count in bins of lanes > t
            #pragma unroll
            for (int j = 7; j >= 0; j--) {
                const unsigned cnt_gt = run;      // candidates in bins > b0+j
                run += hist[b0 + j];
                if (cnt_gt < KSEL && run >= KSEL) { s_B = b0 + j; s_r = KSEL - cnt_gt; }
            }
        }
        __syncthreads();

        float    tv;       // threshold value
        unsigned tcol;     // threshold column (tie-break)
        bool fast = (s_total >= KSEL);

        if (fast) {
            const int      B = (int)s_B;
            const unsigned r = s_r;               // rank needed inside bin B
            const float  fB  = (float)B;
            const float  fB1 = fB + 1.0f;
            const bool   topbin = (B == 255);

            // ---- pass 2: gather bin-B elements via exact float interval ----
            #pragma unroll
            for (int i = 0; i < PER_THREAD; i++) {
                const float g = gmap(vals[i]);
                if (g >= fB && (g < fB1 || topbin)) {
                    const unsigned p = atomicAdd(&s_m, 1u);
                    if (p < MCAP) {
                        mvals[p] = vals[i];
                        mcols[p] = (unsigned short)(4 * t + 1024 * (i >> 2) + (i & 3));
                    }
                }
            }
            __syncthreads();
            const unsigned m = s_m;

            if (m <= MCAP) {
                // exact augmented ranking (value desc, col asc): unique winner
                if (t < (int)m) {
                    const float    c  = mvals[t];
                    const unsigned cc = mcols[t];
                    unsigned gt = 0, eq = 0;
                    for (unsigned j = 0; j < m; j++) {
                        const float    oj = mvals[j];
                        const unsigned oc = mcols[j];
                        eq += (oj == c);
                        gt += (oj > c) || (oj == c && oc < cc);
                    }
                    if (gt == r - 1) {
                        s_thresh = c; s_tcol = cc; s_simple = (eq == 1u);
                    }
                }
                __syncthreads();
                tv   = s_thresh;
                tcol = s_tcol;
            } else {
                fast = false;   // degenerate tie pile-up in one bin
            }
        }

        if (!fast) {
            // ---- exact 4-pass radix-256 select (practically never runs) ----
            unsigned keys[PER_THREAD];
            #pragma unroll
            for (int i = 0; i < PER_THREAD; i++) keys[i] = f2key(vals[i]);

            unsigned prefix = 0, kth = KSEL;
            for (int pass = 0; pass < 4; pass++) {
                const int shift = 24 - 8 * pass;
                const unsigned pmask = pass ? (0xFFFFFFFFu << (shift + 8)) : 0u;
                __syncthreads();
                hist[t] = 0;
                __syncthreads();
                #pragma unroll
                for (int i = 0; i < PER_THREAD; i++) {
                    if ((keys[i] & pmask) == prefix)
                        atomicAdd(&hist[(keys[i] >> shift) & 0xFFu], 1u);
                }
                __syncthreads();
                if (t == 0) {
                    unsigned acc = 0;
                    int b = 256;
                    do { b--; acc += hist[b]; } while (acc < kth && b > 0);
                    s_prefix = prefix | ((unsigned)b << shift);
                    s_kth    = kth - (acc - hist[b]);
                }
                __syncthreads();
                prefix = s_prefix;
                kth    = s_kth;
            }
            const float fv = key2f(prefix);       // exact threshold value
            // deterministic tie resolve by column: histogram ties by col>>4
            __syncthreads();
            hist[t] = 0;
            if (t == 0) { s_m = 0; s_thresh = fv; s_simple = 0; }
            __syncthreads();
            #pragma unroll
            for (int i = 0; i < PER_THREAD; i++) {
                if (vals[i] == fv)
                    atomicAdd(&hist[(4 * t + 1024 * (i >> 2) + (i & 3)) >> 4], 1u);
            }
            __syncthreads();
            if (t == 0) {   // ascending col-bin scan: bin holding rank 'kth'
                unsigned cum = 0; int b = 0;
                while (cum + hist[b] < kth && b < 255) { cum += hist[b]; b++; }
                s_B = (unsigned)b;
                s_r = kth - cum;                  // rank within the col-bin
            }
            __syncthreads();
            #pragma unroll
            for (int i = 0; i < PER_THREAD; i++) {
                const unsigned col = 4 * t + 1024 * (i >> 2) + (i & 3);
                if (vals[i] == fv && (col >> 4) == s_B) {
                    const unsigned p = atomicAdd(&s_m, 1u);   // <= 16 per bin
                    mcols[p] = (unsigned short)col;
                }
            }
            __syncthreads();
            const unsigned m = s_m;
            if (t < (int)m) {                     // rank ties ascending by col
                const unsigned myc = mcols[t];
                unsigned lower = 0;
                for (unsigned j = 0; j < m; j++) lower += (mcols[j] < myc);
                if (lower == s_r - 1) s_tcol = myc;   // unique writer
            }
            __syncthreads();
            tv   = s_thresh;
            tcol = s_tcol;
        }

        // ---- masked streaming write: deterministic, no atomics ----
        float4* orow = reinterpret_cast<float4*>(out + (size_t)row * FDIM);
        if (s_simple) {
            // threshold value unique in the row: single compare per element
            #pragma unroll
            for (int v = 0; v < 4; v++) {
                float4 o;
                o.x = (vals[v*4+0] >= tv) ? vals[v*4+0] : 0.0f;
                o.y = (vals[v*4+1] >= tv) ? vals[v*4+1] : 0.0f;
                o.z = (vals[v*4+2] >= tv) ? vals[v*4+2] : 0.0f;
                o.w = (vals[v*4+3] >= tv) ? vals[v*4+3] : 0.0f;
                __stcs(&orow[t + v * THREADS], o);
            }
        } else {
            // exact stable tie-break (value desc, col asc)
            #pragma unroll
            for (int v = 0; v < 4; v++) {
                float4 o;
                float* op = &o.x;
                #pragma unroll
                for (int j = 0; j < 4; j++) {
                    const float    val = vals[v * 4 + j];
                    const unsigned col = 4 * t + 1024 * v + j;
                    const bool keep = (val > tv) || (val == tv && col <= tcol);
                    op[j] = keep ? val : 0.0f;
                }
                __stcs(&orow[t + v * THREADS], o);
            }
        }
    }
}

extern "C" void kernel_launch(void* const* d_in, const int* in_sizes, int n_in,
                              void* d_out, int out_size) {
    const float* x = (const float*)d_in[0];
    float* out     = (float*)d_out;
    const int B    = in_sizes[0] / FDIM;   // 16384
    const int grid = (B < NCTA) ? B : NCTA;
    topk_mask_kernel<<<grid, THREADS>>>(x, out, B);
}

// round 13
// speedup vs baseline: 1.5487x; 1.5487x over previous
#include <cuda_runtime.h>
#include <stdint.h>

// TopK masking: out = x * mask(top-64 per row), x: [16384, 4096] fp32.
//
// One CTA per row, 256 threads, 16 floats/thread in registers (R11 shape:
// 32 regs, ~92% occupancy, streaming cache ops). Selection over the
// augmented key (value desc, col asc) == jax.lax.top_k stable order ->
// bit-deterministic.
// Store critical path shortened: right after the scan identifies the
// boundary bin B, ALL outputs are stored provisionally (bins > B kept,
// everything else zero) so the write stream overlaps the gather/rank
// phase; then only the few float4 quads containing a bin-B element are
// re-stored with the exact threshold predicate (same thread+address ->
// deterministic final value).
// Exact radix-256 fallback (full exact store) for any out-of-range case.

#define THREADS 256
#define FDIM 4096
#define PER_THREAD 16
#define KSEL 64u
#define TGUESS 1.9f
#define MCAP 256u

__device__ __forceinline__ unsigned int f2key(float f) {
    unsigned int b = __float_as_uint(f);
    return (b & 0x80000000u) ? ~b : (b | 0x80000000u);
}
__device__ __forceinline__ float key2f(unsigned int k) {
    return (k & 0x80000000u) ? __uint_as_float(k & 0x7FFFFFFFu)
                             : __uint_as_float(~k);
}
// deterministic bin: identical fma at every call site; candidates (v>1.9f)
// always have g>0, so trunc == floor and bins form float intervals.
__device__ __forceinline__ float gmap(float v) {
    return __fmaf_rn(v, 100.0f, -190.0f);
}
__device__ __forceinline__ int vbin(float v) {
    int b = (int)gmap(v);
    return b > 255 ? 255 : b;
}

__global__ void __launch_bounds__(THREADS, 8)
topk_mask_kernel(const float* __restrict__ x, float* __restrict__ out) {
    const int row = blockIdx.x;
    const int t   = threadIdx.x;

    __shared__ unsigned int   hist[256];
    __shared__ float          mvals[MCAP];
    __shared__ unsigned short mcols[MCAP];
    __shared__ unsigned int   s_total, s_m, s_B, s_r;
    __shared__ float          s_thresh;
    __shared__ unsigned int   s_tcol, s_simple;
    __shared__ unsigned int   s_prefix, s_kth;   // fallback

    if (t == 0) s_m = 0;
    hist[t] = 0;

    const float4* xrow = reinterpret_cast<const float4*>(x + (size_t)row * FDIM);
    float4*       orow = reinterpret_cast<float4*>(out + (size_t)row * FDIM);

    // ---- streaming load; vals[v*4+j] is column (4t + 1024v + j) ----
    float vals[PER_THREAD];
    #pragma unroll
    for (int v = 0; v < 4; v++) {
        const float4 f4 = __ldcs(&xrow[t + v * THREADS]);
        vals[v * 4 + 0] = f4.x;
        vals[v * 4 + 1] = f4.y;
        vals[v * 4 + 2] = f4.z;
        vals[v * 4 + 3] = f4.w;
    }
    __syncthreads();

    // ---- pass 1: histogram candidates straight from registers ----
    #pragma unroll
    for (int i = 0; i < PER_THREAD; i++) {
        const float v = vals[i];
        if (v > TGUESS) atomicAdd(&hist[vbin(v)], 1u);
    }
    __syncthreads();

    // ---- warp 0: suffix-scan over 256 bins; find rank-KSEL bin + total ----
    if (t < 32) {
        const int b0 = t * 8;
        unsigned lsum = 0;
        #pragma unroll
        for (int j = 0; j < 8; j++) lsum += hist[b0 + j];
        unsigned suf = lsum;                      // becomes sum over lanes >= t
        #pragma unroll
        for (int d = 1; d < 32; d <<= 1) {
            const unsigned v = __shfl_down_sync(0xFFFFFFFFu, suf, d);
            if (t + d < 32) suf += v;
        }
        if (t == 0) s_total = suf;                // total candidates
        unsigned run = suf - lsum;                // count in bins of lanes > t
        #pragma unroll
        for (int j = 7; j >= 0; j--) {
            const unsigned cnt_gt = run;          // candidates in bins > b0+j
            run += hist[b0 + j];
            if (cnt_gt < KSEL && run >= KSEL) { s_B = b0 + j; s_r = KSEL - cnt_gt; }
        }
    }
    __syncthreads();

    bool fast = (s_total >= KSEL);

    if (fast) {
        const int      B = (int)s_B;
        const unsigned r = s_r;                   // rank needed inside bin B
        const float  fB  = (float)B;
        const float  fB1 = fB + 1.0f;
        const bool   topbin = (B == 255);

        // ---- provisional store: bins > B kept, everything else zeroed ----
        // (starts the 256MB write stream 2 barriers early; the few bin-B
        //  quads are corrected below after the exact rank resolves)
        #pragma unroll
        for (int v = 0; v < 4; v++) {
            float4 o;
            float* op = &o.x;
            #pragma unroll
            for (int j = 0; j < 4; j++) {
                const float val = vals[v * 4 + j];
                const bool keep = (gmap(val) >= fB1) && !topbin;  // bin > B
                op[j] = keep ? val : 0.0f;
            }
            __stcs(&orow[t + v * THREADS], o);
        }

        // ---- gather bin-B elements via exact float interval ----
        #pragma unroll
        for (int i = 0; i < PER_THREAD; i++) {
            const float g = gmap(vals[i]);
            if (g >= fB && (g < fB1 || topbin)) {
                const unsigned p = atomicAdd(&s_m, 1u);
                if (p < MCAP) {
                    mvals[p] = vals[i];
                    mcols[p] = (unsigned short)(4 * t + 1024 * (i >> 2) + (i & 3));
                }
            }
        }
        __syncthreads();
        const unsigned m = s_m;

        if (m <= MCAP) {
            // exact augmented ranking (value desc, col asc): unique winner.
            // equal values share a bin, so eq-count here == row-wide tie count.
            if (t < (int)m) {
                const float    c  = mvals[t];
                const unsigned cc = mcols[t];
                unsigned gt = 0, eq = 0;
                for (unsigned j = 0; j < m; j++) {
                    const float    oj = mvals[j];
                    const unsigned oc = mcols[j];
                    eq += (oj == c);
                    gt += (oj > c) || (oj == c && oc < cc);
                }
                if (gt == r - 1) {
                    s_thresh = c; s_tcol = cc; s_simple = (eq == 1u);
                }
            }
            __syncthreads();
            const float    tv   = s_thresh;
            const unsigned tcol = s_tcol;

            // ---- rewrite only quads containing a bin-B element ----
            if (s_simple) {
                #pragma unroll
                for (int v = 0; v < 4; v++) {
                    bool any = false;
                    float4 o;
                    float* op = &o.x;
                    #pragma unroll
                    for (int j = 0; j < 4; j++) {
                        const float val = vals[v * 4 + j];
                        const float g   = gmap(val);
                        any |= (g >= fB && (g < fB1 || topbin));
                        op[j] = (val >= tv) ? val : 0.0f;
                    }
                    if (any) __stcs(&orow[t + v * THREADS], o);
                }
            } else {
                #pragma unroll
                for (int v = 0; v < 4; v++) {
                    bool any = false;
                    float4 o;
                    float* op = &o.x;
                    #pragma unroll
                    for (int j = 0; j < 4; j++) {
                        const float    val = vals[v * 4 + j];
                        const float    g   = gmap(val);
                        const unsigned col = 4 * t + 1024 * v + j;
                        any |= (g >= fB && (g < fB1 || topbin));
                        const bool keep = (val > tv) || (val == tv && col <= tcol);
                        op[j] = keep ? val : 0.0f;
                    }
                    if (any) __stcs(&orow[t + v * THREADS], o);
                }
            }
        } else {
            fast = false;   // degenerate tie pile-up: exact fallback re-stores all
        }
    }

    if (!fast) {
        // ---- exact 4-pass radix-256 select (practically never runs) ----
        unsigned keys[PER_THREAD];
        #pragma unroll
        for (int i = 0; i < PER_THREAD; i++) keys[i] = f2key(vals[i]);

        unsigned prefix = 0, kth = KSEL;
        for (int pass = 0; pass < 4; pass++) {
            const int shift = 24 - 8 * pass;
            const unsigned pmask = pass ? (0xFFFFFFFFu << (shift + 8)) : 0u;
            __syncthreads();
            hist[t] = 0;
            __syncthreads();
            #pragma unroll
            for (int i = 0; i < PER_THREAD; i++) {
                if ((keys[i] & pmask) == prefix)
                    atomicAdd(&hist[(keys[i] >> shift) & 0xFFu], 1u);
            }
            __syncthreads();
            if (t == 0) {
                unsigned acc = 0;
                int b = 256;
                do { b--; acc += hist[b]; } while (acc < kth && b > 0);
                s_prefix = prefix | ((unsigned)b << shift);
                s_kth    = kth - (acc - hist[b]);
            }
            __syncthreads();
            prefix = s_prefix;
            kth    = s_kth;
        }
        const float fv = key2f(prefix);           // exact threshold value
        // deterministic tie resolve by column: histogram ties by col>>4
        __syncthreads();
        hist[t] = 0;
        if (t == 0) { s_m = 0; s_thresh = fv; s_simple = 0; }
        __syncthreads();
        #pragma unroll
        for (int i = 0; i < PER_THREAD; i++) {
            if (vals[i] == fv)
                atomicAdd(&hist[(4 * t + 1024 * (i >> 2) + (i & 3)) >> 4], 1u);
        }
        __syncthreads();
        if (t == 0) {   // ascending col-bin scan: find bin holding rank 'kth'
            unsigned cum = 0; int b = 0;
            while (cum + hist[b] < kth && b < 255) { cum += hist[b]; b++; }
            s_B = (unsigned)b;
            s_r = kth - cum;                      // rank within the col-bin
        }
        __syncthreads();
        #pragma unroll
        for (int i = 0; i < PER_THREAD; i++) {
            const unsigned col = 4 * t + 1024 * (i >> 2) + (i & 3);
            if (vals[i] == fv && (col >> 4) == s_B) {
                const unsigned p = atomicAdd(&s_m, 1u);   // <= 16 per bin
                mcols[p] = (unsigned short)col;
            }
        }
        __syncthreads();
        const unsigned m = s_m;
        if (t < (int)m) {                         // rank ties ascending by col
            const unsigned myc = mcols[t];
            unsigned lower = 0;
            for (unsigned j = 0; j < m; j++) lower += (mcols[j] < myc);
            if (lower == s_r - 1) s_tcol = myc;   // unique writer
        }
        __syncthreads();
        const float    tv   = s_thresh;
        const unsigned tcol = s_tcol;

        // full exact store (overwrites any provisional values)
        #pragma unroll
        for (int v = 0; v < 4; v++) {
            float4 o;
            float* op = &o.x;
            #pragma unroll
            for (int j = 0; j < 4; j++) {
                const float    val = vals[v * 4 + j];
                const unsigned col = 4 * t + 1024 * v + j;
                const bool keep = (val > tv) || (val == tv && col <= tcol);
                op[j] = keep ? val : 0.0f;
            }
            __stcs(&orow[t + v * THREADS], o);
        }
    }
}

extern "C" void kernel_launch(void* const* d_in, const int* in_sizes, int n_in,
                              void* d_out, int out_size) {
    const float* x = (const float*)d_in[0];
    float* out     = (float*)d_out;
    const int B    = in_sizes[0] / FDIM;   // 16384
    topk_mask_kernel<<<B, THREADS>>>(x, out);
}

// round 14
// speedup vs baseline: 1.5995x; 1.0328x over previous
#include <cuda_runtime.h>
#include <stdint.h>

// TopK masking: out = x * mask(top-64 per row), x: [16384, 4096] fp32.
//
// One CTA per row, 256 threads, 16 floats/thread in registers (R11 shape:
// 32 regs, ~92% occupancy, streaming cache ops), with the histogram fused
// into the load loop so binning executes under the load-latency shadow.
// Selection over the augmented key (value desc, col asc) == jax.lax.top_k's
// stable order -> bit-deterministic output.
// Fast path: histogram-256 over (1.9,4.46), warp-0 shuffle suffix-scan ->
// rank-64 bin + total, boundary-bin gather via exact float interval,
// exact augmented rank (unique winner), unique-threshold single-compare
// write. Exact radix-256 fallback for any out-of-range case.
// One GMEM read + one GMEM write per element.

#define THREADS 256
#define FDIM 4096
#define PER_THREAD 16
#define KSEL 64u
#define TGUESS 1.9f
#define MCAP 256u

__device__ __forceinline__ unsigned int f2key(float f) {
    unsigned int b = __float_as_uint(f);
    return (b & 0x80000000u) ? ~b : (b | 0x80000000u);
}
__device__ __forceinline__ float key2f(unsigned int k) {
    return (k & 0x80000000u) ? __uint_as_float(k & 0x7FFFFFFFu)
                             : __uint_as_float(~k);
}
// deterministic bin: identical fma at every call site; candidates (v>1.9f)
// always have g>0, so trunc == floor and bins form float intervals.
__device__ __forceinline__ float gmap(float v) {
    return __fmaf_rn(v, 100.0f, -190.0f);
}
__device__ __forceinline__ int vbin(float v) {
    int b = (int)gmap(v);
    return b > 255 ? 255 : b;
}

__global__ void __launch_bounds__(THREADS, 8)
topk_mask_kernel(const float* __restrict__ x, float* __restrict__ out) {
    const int row = blockIdx.x;
    const int t   = threadIdx.x;

    __shared__ unsigned int   hist[256];
    __shared__ float          mvals[MCAP];
    __shared__ unsigned short mcols[MCAP];
    __shared__ unsigned int   s_total, s_m, s_B, s_r;
    __shared__ float          s_thresh;
    __shared__ unsigned int   s_tcol, s_simple;
    __shared__ unsigned int   s_prefix, s_kth;   // fallback

    if (t == 0) s_m = 0;
    hist[t] = 0;
    __syncthreads();   // zeros visible before any atomics (nothing in flight)

    const float4* xrow = reinterpret_cast<const float4*>(x + (size_t)row * FDIM);
    float4*       orow = reinterpret_cast<float4*>(out + (size_t)row * FDIM);

    // ---- fused streaming load + histogram; vals[v*4+j] = col 4t+1024v+j ----
    // binning of quad v executes while quads v+1.. are still in flight.
    float vals[PER_THREAD];
    #pragma unroll
    for (int v = 0; v < 4; v++) {
        const float4 f4 = __ldcs(&xrow[t + v * THREADS]);
        vals[v * 4 + 0] = f4.x;
        vals[v * 4 + 1] = f4.y;
        vals[v * 4 + 2] = f4.z;
        vals[v * 4 + 3] = f4.w;
        if (f4.x > TGUESS) atomicAdd(&hist[vbin(f4.x)], 1u);
        if (f4.y > TGUESS) atomicAdd(&hist[vbin(f4.y)], 1u);
        if (f4.z > TGUESS) atomicAdd(&hist[vbin(f4.z)], 1u);
        if (f4.w > TGUESS) atomicAdd(&hist[vbin(f4.w)], 1u);
    }
    __syncthreads();

    // ---- warp 0: suffix-scan over 256 bins; find rank-KSEL bin + total ----
    if (t < 32) {
        const int b0 = t * 8;
        unsigned lsum = 0;
        #pragma unroll
        for (int j = 0; j < 8; j++) lsum += hist[b0 + j];
        unsigned suf = lsum;                      // becomes sum over lanes >= t
        #pragma unroll
        for (int d = 1; d < 32; d <<= 1) {
            const unsigned v = __shfl_down_sync(0xFFFFFFFFu, suf, d);
            if (t + d < 32) suf += v;
        }
        if (t == 0) s_total = suf;                // total candidates
        unsigned run = suf - lsum;                // count in bins of lanes > t
        #pragma unroll
        for (int j = 7; j >= 0; j--) {
            const unsigned cnt_gt = run;          // candidates in bins > b0+j
            run += hist[b0 + j];
            if (cnt_gt < KSEL && run >= KSEL) { s_B = b0 + j; s_r = KSEL - cnt_gt; }
        }
    }
    __syncthreads();

    float    tv;       // threshold value
    unsigned tcol;     // threshold column (tie-break)
    bool fast = (s_total >= KSEL);

    if (fast) {
        const int      B = (int)s_B;
        const unsigned r = s_r;                   // rank needed inside bin B
        const float  fB  = (float)B;
        const float  fB1 = fB + 1.0f;
        const bool   topbin = (B == 255);

        // ---- gather bin-B elements via exact float interval ----
        #pragma unroll
        for (int i = 0; i < PER_THREAD; i++) {
            const float g = gmap(vals[i]);
            if (g >= fB && (g < fB1 || topbin)) {
                const unsigned p = atomicAdd(&s_m, 1u);
                if (p < MCAP) {
                    mvals[p] = vals[i];
                    mcols[p] = (unsigned short)(4 * t + 1024 * (i >> 2) + (i & 3));
                }
            }
        }
        __syncthreads();
        const unsigned m = s_m;

        if (m <= MCAP) {
            // exact augmented ranking (value desc, col asc): unique winner.
            // equal values share a bin, so eq-count here == row-wide tie count.
            if (t < (int)m) {
                const float    c  = mvals[t];
                const unsigned cc = mcols[t];
                unsigned gt = 0, eq = 0;
                for (unsigned j = 0; j < m; j++) {
                    const float    oj = mvals[j];
                    const unsigned oc = mcols[j];
                    eq += (oj == c);
                    gt += (oj > c) || (oj == c && oc < cc);
                }
                if (gt == r - 1) {
                    s_thresh = c; s_tcol = cc; s_simple = (eq == 1u);
                }
            }
            __syncthreads();
            tv   = s_thresh;
            tcol = s_tcol;
        } else {
            fast = false;   // degenerate tie pile-up in one bin
        }
    }

    if (!fast) {
        // ---- exact 4-pass radix-256 select (practically never runs) ----
        unsigned keys[PER_THREAD];
        #pragma unroll
        for (int i = 0; i < PER_THREAD; i++) keys[i] = f2key(vals[i]);

        unsigned prefix = 0, kth = KSEL;
        for (int pass = 0; pass < 4; pass++) {
            const int shift = 24 - 8 * pass;
            const unsigned pmask = pass ? (0xFFFFFFFFu << (shift + 8)) : 0u;
            __syncthreads();
            hist[t] = 0;
            __syncthreads();
            #pragma unroll
            for (int i = 0; i < PER_THREAD; i++) {
                if ((keys[i] & pmask) == prefix)
                    atomicAdd(&hist[(keys[i] >> shift) & 0xFFu], 1u);
            }
            __syncthreads();
            if (t == 0) {
                unsigned acc = 0;
                int b = 256;
                do { b--; acc += hist[b]; } while (acc < kth && b > 0);
                s_prefix = prefix | ((unsigned)b << shift);
                s_kth    = kth - (acc - hist[b]);
            }
            __syncthreads();
            prefix = s_prefix;
            kth    = s_kth;
        }
        const float fv = key2f(prefix);           // exact threshold value
        // deterministic tie resolve by column: histogram ties by col>>4
        __syncthreads();
        hist[t] = 0;
        if (t == 0) { s_m = 0; s_thresh = fv; s_simple = 0; }
        __syncthreads();
        #pragma unroll
        for (int i = 0; i < PER_THREAD; i++) {
            if (vals[i] == fv)
                atomicAdd(&hist[(4 * t + 1024 * (i >> 2) + (i & 3)) >> 4], 1u);
        }
        __syncthreads();
        if (t == 0) {   // ascending col-bin scan: find bin holding rank 'kth'
            unsigned cum = 0; int b = 0;
            while (cum + hist[b] < kth && b < 255) { cum += hist[b]; b++; }
            s_B = (unsigned)b;
            s_r = kth - cum;                      // rank within the col-bin
        }
        __syncthreads();
        #pragma unroll
        for (int i = 0; i < PER_THREAD; i++) {
            const unsigned col = 4 * t + 1024 * (i >> 2) + (i & 3);
            if (vals[i] == fv && (col >> 4) == s_B) {
                const unsigned p = atomicAdd(&s_m, 1u);   // <= 16 per bin
                mcols[p] = (unsigned short)col;
            }
        }
        __syncthreads();
        const unsigned m = s_m;
        if (t < (int)m) {                         // rank ties ascending by col
            const unsigned myc = mcols[t];
            unsigned lower = 0;
            for (unsigned j = 0; j < m; j++) lower += (mcols[j] < myc);
            if (lower == s_r - 1) s_tcol = myc;   // unique writer
        }
        __syncthreads();
        tv   = s_thresh;
        tcol = s_tcol;
    }

    // ---- masked streaming write: deterministic, no atomics ----
    if (s_simple) {
        // threshold value is unique in the row: single compare per element
        #pragma unroll
        for (int v = 0; v < 4; v++) {
            float4 o;
            o.x = (vals[v*4+0] >= tv) ? vals[v*4+0] : 0.0f;
            o.y = (vals[v*4+1] >= tv) ? vals[v*4+1] : 0.0f;
            o.z = (vals[v*4+2] >= tv) ? vals[v*4+2] : 0.0f;
            o.w = (vals[v*4+3] >= tv) ? vals[v*4+3] : 0.0f;
            __stcs(&orow[t + v * THREADS], o);
        }
    } else {
        // exact stable tie-break (value desc, col asc)
        #pragma unroll
        for (int v = 0; v < 4; v++) {
            float4 o;
            float* op = &o.x;
            #pragma unroll
            for (int j = 0; j < 4; j++) {
                const float    val = vals[v * 4 + j];
                const unsigned col = 4 * t + 1024 * v + j;
                const bool keep = (val > tv) || (val == tv && col <= tcol);
                op[j] = keep ? val : 0.0f;
            }
            __stcs(&orow[t + v * THREADS], o);
        }
    }
}

extern "C" void kernel_launch(void* const* d_in, const int* in_sizes, int n_in,
                              void* d_out, int out_size) {
    const float* x = (const float*)d_in[0];
    float* out     = (float*)d_out;
    const int B    = in_sizes[0] / FDIM;   // 16384
    topk_mask_kernel<<<B, THREADS>>>(x, out);
}